// round 14
// baseline (speedup 1.0000x reference)
#include <cuda_runtime.h>
#include <cuda_bf16.h>
#include <float.h>
#include <stdint.h>

// Fixed problem shape
#define KC      512
#define DC      64
#define HWC     4096
#define NC      131072
#define TPB     256         // 8 warps
#define PIX     128         // pixels per tile
#define NTILES  (NC/PIX)    // 1024
#define GRIDP   256         // 2 CTAs/SM; dynamic tile stealing
#define EPITCH  72          // bf16 codebook pitch
#define FPITCH  66          // fp32 latent pitch
#define WLCAP   768

// smem layout (bytes)
#define OFF_ECB 0                           // bf16 [512][72]   73728
#define OFF_F32 (OFF_ECB + KC*EPITCH*2)     // fp32 [128][66]   33792
#define OFF_EN  (OFF_F32 + PIX*FPITCH*4)    // float[512]        2048
#define OFF_FN  (OFF_EN + KC*4)             // float[128]         512
#define OFF_SLK (OFF_FN + PIX*4)            // float[128]         512
#define OFF_BND (OFF_SLK + PIX*4)           // float[256]        1024
#define OFF_BST (OFF_BND + TPB*4)           // u64  [128]        1024
#define OFF_PXO (OFF_BST + PIX*8)           // uchar[128]         128
#define OFF_WL  (OFF_PXO + 128)             // u32  [768]        3072 (red overlays)
#define OFF_CNT (OFF_WL + WLCAP*4)          // int + pad           16
#define SMEM_BYTES (OFF_CNT + 16)           // 115856 <= 116736 (2/SM)

__device__ float    g_part[NTILES];
__device__ unsigned g_done;
__device__ unsigned g_tile;

__device__ __forceinline__ void mma_bf16(float c[4], const unsigned a[4],
                                         unsigned b0, unsigned b1) {
    asm volatile(
        "mma.sync.aligned.m16n8k16.row.col.f32.bf16.bf16.f32 "
        "{%0,%1,%2,%3}, {%4,%5,%6,%7}, {%8,%9}, {%0,%1,%2,%3};"
        : "+f"(c[0]), "+f"(c[1]), "+f"(c[2]), "+f"(c[3])
        : "r"(a[0]), "r"(a[1]), "r"(a[2]), "r"(a[3]), "r"(b0), "r"(b1));
}

__device__ __forceinline__ unsigned pack_bf2(float2 p) {
    __nv_bfloat162 h = __float22bfloat162_rn(p);
    return *reinterpret_cast<unsigned*>(&h);
}

// exact reference-arithmetic distance for (pixel fr, code k)
__device__ __forceinline__ float exact_dist(const float* fr, const float* emb,
                                            float fn, float en, int k) {
    const float4* er4 = (const float4*)(emb + (size_t)k * DC);
    float dot = 0.0f;
    #pragma unroll
    for (int q = 0; q < 16; ++q) {
        float4 ev = __ldg(er4 + q);
        dot = fmaf(fr[4 * q + 0], ev.x, dot);
        dot = fmaf(fr[4 * q + 1], ev.y, dot);
        dot = fmaf(fr[4 * q + 2], ev.z, dot);
        dot = fmaf(fr[4 * q + 3], ev.w, dot);
    }
    return __fsub_rn(__fadd_rn(fn, en), __fmul_rn(2.0f, dot));
}

__device__ __forceinline__ unsigned long long dist_key(float r, int k) {
    unsigned rb = __float_as_uint(r);
    rb ^= (rb >> 31) ? 0xFFFFFFFFu : 0x80000000u;   // order-preserving map
    return ((unsigned long long)rb << 32) | (unsigned)k;
}

__global__ __launch_bounds__(TPB, 2)
void vq_kernel(const float* __restrict__ latents,
               const float* __restrict__ embedding,
               float* __restrict__ out,
               float* __restrict__ loss_out) {
    extern __shared__ char smem[];
    __nv_bfloat16* Ecb = (__nv_bfloat16*)(smem + OFF_ECB);
    float* F32  = (float*)(smem + OFF_F32);
    float* enS  = (float*)(smem + OFF_EN);
    float* fnS  = (float*)(smem + OFF_FN);
    float* slkS = (float*)(smem + OFF_SLK);
    float* bndS = (float*)(smem + OFF_BND);
    unsigned long long* bestS = (unsigned long long*)(smem + OFF_BST);
    unsigned char* pxovf = (unsigned char*)(smem + OFF_PXO);
    unsigned* wl   = (unsigned*)(smem + OFF_WL);
    int*      wcnt = (int*)(smem + OFF_CNT);
    float*    red  = (float*)(smem + OFF_WL);   // overlay after wl dead

    const int tid  = threadIdx.x;
    const int wid  = tid >> 5;
    const int lane = tid & 31;
    const int g    = lane >> 2;
    const int tig  = lane & 3;
    const int px   = tid & (PIX - 1);   // pixel for split phases
    const int hh   = tid >> 7;          // half (0:d<32, 1:d>=32)

    // ---- once per CTA: bf16 codebook + exact reference enorm ----
    for (int i = tid; i < KC * DC; i += TPB) {
        int k = i >> 6, d = i & 63;
        Ecb[k * EPITCH + d] = __float2bfloat16_rn(embedding[i]);
    }
    #pragma unroll
    for (int kk = 0; kk < 2; ++kk) {
        int k = tid + kk * TPB;
        const float* er = embedding + (size_t)k * DC;
        float s = 0.0f;
        #pragma unroll
        for (int d = 0; d < DC; ++d)
            s = __fadd_rn(s, __fmul_rn(er[d], er[d]));
        enS[k] = s;
    }
    __syncthreads();

    __shared__ int  s_tile;
    __shared__ bool s_govf;

    while (true) {
        if (tid == 0) s_tile = (int)atomicAdd(&g_tile, 1u);
        __syncthreads();
        const int tile = s_tile;
        if (tile >= NTILES) break;

        const int P  = tile * PIX + px;
        const int b  = P >> 12;
        const int hw = P & (HWC - 1);
        const float* lat = latents + (size_t)b * DC * HWC + hw;

        // ---- phase 0: stage latents (all 256 threads, half-pixel each) ----
        {
            float bnd = 0.0f;
            float* fr = F32 + px * FPITCH;
            #pragma unroll
            for (int j = 0; j < 32; ++j) {
                int d = hh * 32 + j;
                float f = lat[d * HWC];
                fr[d] = f;
                float fb = __bfloat162float(__float2bfloat16_rn(f));
                bnd += fabsf(f) * 4.0e-6f + 1.96e-3f * fabsf(f - fb);
            }
            bndS[tid] = bnd;
            if (tid < PIX) { bestS[tid] = 0xFFFFFFFFFFFFFFFFull; pxovf[tid] = 0; }
            if (tid == 0)  { *wcnt = 0; s_govf = false; }
        }
        __syncthreads();

        // ---- fnorm (exact sequential chain) + slack ----
        if (tid < PIX) {
            const float* fr = F32 + tid * FPITCH;
            float fn = 0.0f;
            #pragma unroll
            for (int d = 0; d < DC; ++d)
                fn = __fadd_rn(fn, __fmul_rn(fr[d], fr[d]));
            fnS[tid]  = fn;
            slkS[tid] = fmaf(5.0f, bndS[tid] + bndS[tid + PIX], 1.6e-4f);
        }
        __syncthreads();

        // ---- A fragments (cvt fp32->bf16 from smem) ----
        const int r0 = wid * 16 + g;
        const int r1 = r0 + 8;
        unsigned afr[4][4];
        #pragma unroll
        for (int ks = 0; ks < 4; ++ks) {
            afr[ks][0] = pack_bf2(*(const float2*)(F32 + r0 * FPITCH + 16 * ks + 2 * tig));
            afr[ks][1] = pack_bf2(*(const float2*)(F32 + r1 * FPITCH + 16 * ks + 2 * tig));
            afr[ks][2] = pack_bf2(*(const float2*)(F32 + r0 * FPITCH + 16 * ks + 8 + 2 * tig));
            afr[ks][3] = pack_bf2(*(const float2*)(F32 + r1 * FPITCH + 16 * ks + 8 + 2 * tig));
        }
        const float slk0 = slkS[r0];
        const float slk1 = slkS[r1];

        // ---- single GEMM pass: screen + inline candidate tracking ----
        float rm0 = FLT_MAX, rm1 = FLT_MAX;
        float cs00 = 0.f, cs01 = 0.f, cs10 = 0.f, cs11 = 0.f;
        int   ck00 = 0, ck01 = 0, ck10 = 0, ck11 = 0;
        int   n0 = 0, n1 = 0;

        #pragma unroll 2
        for (int nb = 0; nb < KC / 8; ++nb) {
            const int cb = nb * 8;
            const __nv_bfloat16* brow = Ecb + (cb + g) * EPITCH;
            float c[4] = {0.f, 0.f, 0.f, 0.f};
            #pragma unroll
            for (int ks = 0; ks < 4; ++ks) {
                unsigned b0 = *(const unsigned*)(brow + 16 * ks + 2 * tig);
                unsigned b1 = *(const unsigned*)(brow + 16 * ks + 8 + 2 * tig);
                mma_bf16(c, afr[ks], b0, b1);
            }
            const int k0 = cb + 2 * tig;
            float en0 = enS[k0];
            float en1 = enS[k0 + 1];
            float s0 = fmaf(-2.0f, c[0], en0);
            float s1 = fmaf(-2.0f, c[1], en1);
            float s2 = fmaf(-2.0f, c[2], en0);
            float s3 = fmaf(-2.0f, c[3], en1);

            rm0 = fminf(rm0, fminf(s0, s1));
            rm1 = fminf(rm1, fminf(s2, s3));
            // candidate capture: s <= runmin + slack  (superset of final set)
            if (s0 <= rm0 + slk0) {
                if      (n0 == 0) { cs00 = s0; ck00 = k0; }
                else if (n0 == 1) { cs01 = s0; ck01 = k0; }
                n0++;
            }
            if (s1 <= rm0 + slk0) {
                if      (n0 == 0) { cs00 = s1; ck00 = k0 + 1; }
                else if (n0 == 1) { cs01 = s1; ck01 = k0 + 1; }
                n0++;
            }
            if (s2 <= rm1 + slk1) {
                if      (n1 == 0) { cs10 = s2; ck10 = k0; }
                else if (n1 == 1) { cs11 = s2; ck11 = k0; }
                n1++;
            }
            if (s3 <= rm1 + slk1) {
                if      (n1 == 0) { cs10 = s3; ck10 = k0 + 1; }
                else if (n1 == 1) { cs11 = s3; ck11 = k0 + 1; }
                n1++;
            }
        }

        // group (pixel) min via shfl over tig
        float gm0 = fminf(rm0, __shfl_xor_sync(0xffffffffu, rm0, 1));
        gm0 = fminf(gm0, __shfl_xor_sync(0xffffffffu, gm0, 2));
        float gm1 = fminf(rm1, __shfl_xor_sync(0xffffffffu, rm1, 1));
        gm1 = fminf(gm1, __shfl_xor_sync(0xffffffffu, gm1, 2));

        // push filtered candidates (or flag pixel on per-thread overflow)
        if (n0 > 2) pxovf[r0] = 1;
        else {
            if (n0 >= 1 && cs00 <= gm0 + slk0) { int p_ = atomicAdd(wcnt, 1); if (p_ < WLCAP) wl[p_] = ((unsigned)r0 << 16) | (unsigned)ck00; }
            if (n0 >= 2 && cs01 <= gm0 + slk0) { int p_ = atomicAdd(wcnt, 1); if (p_ < WLCAP) wl[p_] = ((unsigned)r0 << 16) | (unsigned)ck01; }
        }
        if (n1 > 2) pxovf[r1] = 1;
        else {
            if (n1 >= 1 && cs10 <= gm1 + slk1) { int p_ = atomicAdd(wcnt, 1); if (p_ < WLCAP) wl[p_] = ((unsigned)r1 << 16) | (unsigned)ck10; }
            if (n1 >= 2 && cs11 <= gm1 + slk1) { int p_ = atomicAdd(wcnt, 1); if (p_ < WLCAP) wl[p_] = ((unsigned)r1 << 16) | (unsigned)ck11; }
        }
        __syncthreads();

        // ---- phase 3: exact recheck ----
        if (tid == 0 && *wcnt > WLCAP) s_govf = true;
        __syncthreads();
        const bool govf = s_govf;
        if (!govf) {
            const int nw = *wcnt;
            for (int i = tid; i < nw; i += TPB) {
                unsigned e = wl[i];
                int pix = (int)(e >> 16);
                int k   = (int)(e & 0xFFFFu);
                float r = exact_dist(F32 + pix * FPITCH, embedding, fnS[pix], enS[k], k);
                atomicMin(&bestS[pix], dist_key(r, k));
            }
        }
        if (tid < PIX && (govf || pxovf[tid])) {
            // fallback: full exact scan for this pixel (correct by construction)
            const float* fr = F32 + tid * FPITCH;
            const float  fn = fnS[tid];
            float best = FLT_MAX; int bestk = 0;
            for (int k = 0; k < KC; ++k) {
                float r = exact_dist(fr, embedding, fn, enS[k], k);
                if (r < best) { best = r; bestk = k; }   // ascending k => first-min
            }
            atomicMin(&bestS[tid], dist_key(best, bestk));
        }
        __syncthreads();

        // ---- phase 4: epilogue, all 256 threads (half pixel each) ----
        float ldist = 0.0f;
        {
            const int bestk = (int)(unsigned)(bestS[px] & 0xFFFFu);
            const float* fr = F32 + px * FPITCH + hh * 32;
            float* outp = out + (size_t)b * DC * HWC + hw + (size_t)(hh * 32) * HWC;
            const float4* er4 = (const float4*)(embedding + (size_t)bestk * DC + hh * 32);
            #pragma unroll
            for (int q = 0; q < 8; ++q) {
                float4 ev = __ldg(er4 + q);
                float f0 = fr[4 * q + 0], f1 = fr[4 * q + 1];
                float f2 = fr[4 * q + 2], f3 = fr[4 * q + 3];
                float d0 = __fsub_rn(ev.x, f0);
                float d1 = __fsub_rn(ev.y, f1);
                float d2 = __fsub_rn(ev.z, f2);
                float d3 = __fsub_rn(ev.w, f3);
                ldist = __fadd_rn(ldist, __fmul_rn(d0, d0));
                ldist = __fadd_rn(ldist, __fmul_rn(d1, d1));
                ldist = __fadd_rn(ldist, __fmul_rn(d2, d2));
                ldist = __fadd_rn(ldist, __fmul_rn(d3, d3));
                outp[(4 * q + 0) * HWC] = __fadd_rn(f0, d0);
                outp[(4 * q + 1) * HWC] = __fadd_rn(f1, d1);
                outp[(4 * q + 2) * HWC] = __fadd_rn(f2, d2);
                outp[(4 * q + 3) * HWC] = __fadd_rn(f3, d3);
            }
        }
        __syncthreads();            // wl dead; red overlay safe

        // ---- per-tile deterministic tree reduce -> g_part[tile] ----
        red[tid] = ldist;
        __syncthreads();
        #pragma unroll
        for (int s = TPB / 2; s > 0; s >>= 1) {
            if (tid < s) red[tid] += red[tid + s];
            __syncthreads();
        }
        if (tid == 0) g_part[tile] = red[0];
        __syncthreads();
    }

    // ---- grid finalize ----
    __shared__ unsigned s_last;
    __threadfence();
    if (tid == 0) s_last = (atomicAdd(&g_done, 1u) == GRIDP - 1u);
    __syncthreads();

    if (s_last) {
        red[tid] = (g_part[tid] + g_part[tid + 256])
                 + (g_part[tid + 512] + g_part[tid + 768]);
        __syncthreads();
        #pragma unroll
        for (int s = TPB / 2; s > 0; s >>= 1) {
            if (tid < s) red[tid] += red[tid + s];
            __syncthreads();
        }
        if (tid == 0) {
            float m = red[0] / 8388608.0f;
            *loss_out = __fadd_rn(__fmul_rn(m, 0.25f), m);
            g_done = 0;
            g_tile = 0;
        }
    }
}

extern "C" void kernel_launch(void* const* d_in, const int* in_sizes, int n_in,
                              void* d_out, int out_size) {
    const float* latents   = (const float*)d_in[0];
    const float* embedding = (const float*)d_in[1];
    float* out  = (float*)d_out;
    float* loss = out + (out_size - 1);

    cudaFuncSetAttribute(vq_kernel, cudaFuncAttributeMaxDynamicSharedMemorySize, SMEM_BYTES);
    vq_kernel<<<GRIDP, TPB, SMEM_BYTES>>>(latents, embedding, out, loss);
}

// round 15
// speedup vs baseline: 1.6160x; 1.6160x over previous
#include <cuda_runtime.h>
#include <cuda_bf16.h>
#include <float.h>
#include <stdint.h>

// Fixed problem shape
#define KC      512
#define DC      64
#define HWC     4096
#define NC      131072
#define TPB     256         // 8 warps
#define PIX     128         // pixels per tile
#define NTILES  (NC/PIX)    // 1024
#define GRIDP   256         // 2 CTAs/SM; dynamic tile stealing
#define EPITCH  72          // bf16 codebook pitch
#define FPITCH  66          // fp32 latent pitch
#define WLCAP   768

// smem layout (bytes)
#define OFF_ECB 0                           // bf16 [512][72]   73728
#define OFF_F32 (OFF_ECB + KC*EPITCH*2)     // fp32 [128][66]   33792
#define OFF_EN  (OFF_F32 + PIX*FPITCH*4)    // float[512]        2048
#define OFF_FN  (OFF_EN + KC*4)             // float[128]         512
#define OFF_SLK (OFF_FN + PIX*4)            // float[128]         512
#define OFF_BND (OFF_SLK + PIX*4)           // float[256]        1024
#define OFF_BST (OFF_BND + TPB*4)           // u64  [128]        1024
#define OFF_PXO (OFF_BST + PIX*8)           // uchar[128]         128
#define OFF_WL  (OFF_PXO + 128)             // u32  [768]        3072 (red overlays)
#define OFF_CNT (OFF_WL + WLCAP*4)          // int + pad           16
#define SMEM_BYTES (OFF_CNT + 16)

__device__ float    g_part[NTILES];
__device__ unsigned g_done;
__device__ unsigned g_tile;

__device__ __forceinline__ void mma_bf16(float c[4], const unsigned a[4],
                                         unsigned b0, unsigned b1) {
    asm volatile(
        "mma.sync.aligned.m16n8k16.row.col.f32.bf16.bf16.f32 "
        "{%0,%1,%2,%3}, {%4,%5,%6,%7}, {%8,%9}, {%0,%1,%2,%3};"
        : "+f"(c[0]), "+f"(c[1]), "+f"(c[2]), "+f"(c[3])
        : "r"(a[0]), "r"(a[1]), "r"(a[2]), "r"(a[3]), "r"(b0), "r"(b1));
}

__device__ __forceinline__ unsigned pack_bf2(float2 p) {
    __nv_bfloat162 h = __float22bfloat162_rn(p);
    return *reinterpret_cast<unsigned*>(&h);
}

// running top-3: v1<=v2<=v3 smallest seen; indices kept for top-2
__device__ __forceinline__ void top3(float s, int k,
                                     float& v1, int& k1, float& v2, int& k2,
                                     float& v3) {
    bool lt1 = s < v1;
    bool lt2 = s < v2;
    bool lt3 = s < v3;
    float nv3 = lt2 ? v2 : (lt3 ? s : v3);
    float nv2 = lt1 ? v1 : (lt2 ? s : v2);
    int   nk2 = lt1 ? k1 : (lt2 ? k : k2);
    float nv1 = lt1 ? s  : v1;
    int   nk1 = lt1 ? k  : k1;
    v1 = nv1; k1 = nk1; v2 = nv2; k2 = nk2; v3 = nv3;
}

// exact reference-arithmetic distance for (pixel fr, code k)
__device__ __forceinline__ float exact_dist(const float* fr, const float* emb,
                                            float fn, float en, int k) {
    const float4* er4 = (const float4*)(emb + (size_t)k * DC);
    float dot = 0.0f;
    #pragma unroll
    for (int q = 0; q < 16; ++q) {
        float4 ev = __ldg(er4 + q);
        dot = fmaf(fr[4 * q + 0], ev.x, dot);
        dot = fmaf(fr[4 * q + 1], ev.y, dot);
        dot = fmaf(fr[4 * q + 2], ev.z, dot);
        dot = fmaf(fr[4 * q + 3], ev.w, dot);
    }
    return __fsub_rn(__fadd_rn(fn, en), __fmul_rn(2.0f, dot));
}

__device__ __forceinline__ unsigned long long dist_key(float r, int k) {
    unsigned rb = __float_as_uint(r);
    rb ^= (rb >> 31) ? 0xFFFFFFFFu : 0x80000000u;   // order-preserving map
    return ((unsigned long long)rb << 32) | (unsigned)k;
}

__global__ __launch_bounds__(TPB, 2)
void vq_kernel(const float* __restrict__ latents,
               const float* __restrict__ embedding,
               float* __restrict__ out,
               float* __restrict__ loss_out) {
    extern __shared__ char smem[];
    __nv_bfloat16* Ecb = (__nv_bfloat16*)(smem + OFF_ECB);
    float* F32  = (float*)(smem + OFF_F32);
    float* enS  = (float*)(smem + OFF_EN);
    float* fnS  = (float*)(smem + OFF_FN);
    float* slkS = (float*)(smem + OFF_SLK);
    float* bndS = (float*)(smem + OFF_BND);
    unsigned long long* bestS = (unsigned long long*)(smem + OFF_BST);
    unsigned char* pxovf = (unsigned char*)(smem + OFF_PXO);
    unsigned* wl   = (unsigned*)(smem + OFF_WL);
    int*      wcnt = (int*)(smem + OFF_CNT);
    float*    red  = (float*)(smem + OFF_WL);   // overlay after wl dead

    const int tid  = threadIdx.x;
    const int wid  = tid >> 5;
    const int lane = tid & 31;
    const int g    = lane >> 2;
    const int tig  = lane & 3;
    const int px   = tid & (PIX - 1);
    const int hh   = tid >> 7;

    // ---- once per CTA: bf16 codebook + exact reference enorm ----
    for (int i = tid; i < KC * DC; i += TPB) {
        int k = i >> 6, d = i & 63;
        Ecb[k * EPITCH + d] = __float2bfloat16_rn(embedding[i]);
    }
    #pragma unroll
    for (int kk = 0; kk < 2; ++kk) {
        int k = tid + kk * TPB;
        const float* er = embedding + (size_t)k * DC;
        float s = 0.0f;
        #pragma unroll
        for (int d = 0; d < DC; ++d)
            s = __fadd_rn(s, __fmul_rn(er[d], er[d]));
        enS[k] = s;
    }
    __syncthreads();

    __shared__ int s_tile;

    while (true) {
        if (tid == 0) s_tile = (int)atomicAdd(&g_tile, 1u);
        __syncthreads();
        const int tile = s_tile;
        if (tile >= NTILES) break;

        const int P  = tile * PIX + px;
        const int b  = P >> 12;
        const int hw = P & (HWC - 1);
        const float* lat = latents + (size_t)b * DC * HWC + hw;

        // ---- phase 0: stage latents (all 256 threads, half-pixel each) ----
        {
            float bnd = 0.0f;
            float* fr = F32 + px * FPITCH;
            #pragma unroll
            for (int j = 0; j < 32; ++j) {
                int d = hh * 32 + j;
                float f = lat[d * HWC];
                fr[d] = f;
                float fb = __bfloat162float(__float2bfloat16_rn(f));
                bnd += fabsf(f) * 4.0e-6f + 1.96e-3f * fabsf(f - fb);
            }
            bndS[tid] = bnd;
            if (tid < PIX) { bestS[tid] = 0xFFFFFFFFFFFFFFFFull; pxovf[tid] = 0; }
            if (tid == 0)  *wcnt = 0;
        }
        __syncthreads();

        // ---- fnorm (exact sequential chain) + slack ----
        if (tid < PIX) {
            const float* fr = F32 + tid * FPITCH;
            float fn = 0.0f;
            #pragma unroll
            for (int d = 0; d < DC; ++d)
                fn = __fadd_rn(fn, __fmul_rn(fr[d], fr[d]));
            fnS[tid]  = fn;
            slkS[tid] = fmaf(5.0f, bndS[tid] + bndS[tid + PIX], 1.6e-4f);
        }
        __syncthreads();

        // ---- A fragments (cvt fp32->bf16 from smem) ----
        const int r0 = wid * 16 + g;
        const int r1 = r0 + 8;
        unsigned afr[4][4];
        #pragma unroll
        for (int ks = 0; ks < 4; ++ks) {
            afr[ks][0] = pack_bf2(*(const float2*)(F32 + r0 * FPITCH + 16 * ks + 2 * tig));
            afr[ks][1] = pack_bf2(*(const float2*)(F32 + r1 * FPITCH + 16 * ks + 2 * tig));
            afr[ks][2] = pack_bf2(*(const float2*)(F32 + r0 * FPITCH + 16 * ks + 8 + 2 * tig));
            afr[ks][3] = pack_bf2(*(const float2*)(F32 + r1 * FPITCH + 16 * ks + 8 + 2 * tig));
        }

        // ---- single GEMM pass with per-thread top-3 tracking ----
        float v10 = FLT_MAX, v20 = FLT_MAX, v30 = FLT_MAX;
        float v11 = FLT_MAX, v21 = FLT_MAX, v31 = FLT_MAX;
        int   k10 = 0, k20 = 0, k11 = 0, k21 = 0;

        #pragma unroll 4
        for (int nb = 0; nb < KC / 8; ++nb) {
            const int cb = nb * 8;
            const __nv_bfloat16* brow = Ecb + (cb + g) * EPITCH;
            float c[4] = {0.f, 0.f, 0.f, 0.f};
            #pragma unroll
            for (int ks = 0; ks < 4; ++ks) {
                unsigned b0 = *(const unsigned*)(brow + 16 * ks + 2 * tig);
                unsigned b1 = *(const unsigned*)(brow + 16 * ks + 8 + 2 * tig);
                mma_bf16(c, afr[ks], b0, b1);
            }
            const int k0 = cb + 2 * tig;
            float en0 = enS[k0];
            float en1 = enS[k0 + 1];
            top3(fmaf(-2.0f, c[0], en0), k0,     v10, k10, v20, k20, v30);
            top3(fmaf(-2.0f, c[1], en1), k0 + 1, v10, k10, v20, k20, v30);
            top3(fmaf(-2.0f, c[2], en0), k0,     v11, k11, v21, k21, v31);
            top3(fmaf(-2.0f, c[3], en1), k0 + 1, v11, k11, v21, k21, v31);
        }

        // pixel min via shfl over the 4 owning threads
        float gm0 = fminf(v10, __shfl_xor_sync(0xffffffffu, v10, 1));
        gm0 = fminf(gm0, __shfl_xor_sync(0xffffffffu, gm0, 2));
        float gm1 = fminf(v11, __shfl_xor_sync(0xffffffffu, v11, 1));
        gm1 = fminf(gm1, __shfl_xor_sync(0xffffffffu, gm1, 2));
        const float thr0 = gm0 + slkS[r0];
        const float thr1 = gm1 + slkS[r1];

        // push candidates; v3<=thr means possible 3rd candidate -> flag pixel
        if (v30 <= thr0) pxovf[r0] = 1;
        else {
            if (v10 <= thr0) { int p_ = atomicAdd(wcnt, 1); if (p_ < WLCAP) wl[p_] = ((unsigned)r0 << 16) | (unsigned)k10; else pxovf[r0] = 1; }
            if (v20 <= thr0) { int p_ = atomicAdd(wcnt, 1); if (p_ < WLCAP) wl[p_] = ((unsigned)r0 << 16) | (unsigned)k20; else pxovf[r0] = 1; }
        }
        if (v31 <= thr1) pxovf[r1] = 1;
        else {
            if (v11 <= thr1) { int p_ = atomicAdd(wcnt, 1); if (p_ < WLCAP) wl[p_] = ((unsigned)r1 << 16) | (unsigned)k11; else pxovf[r1] = 1; }
            if (v21 <= thr1) { int p_ = atomicAdd(wcnt, 1); if (p_ < WLCAP) wl[p_] = ((unsigned)r1 << 16) | (unsigned)k21; else pxovf[r1] = 1; }
        }
        __syncthreads();

        // ---- phase 3: parallel exact recheck over pushed pairs ----
        {
            int nw = *wcnt;
            if (nw > WLCAP) nw = WLCAP;
            for (int i = tid; i < nw; i += TPB) {
                unsigned e = wl[i];
                int pix = (int)(e >> 16);
                int k   = (int)(e & 0xFFFFu);
                if (!pxovf[pix]) {
                    float r = exact_dist(F32 + pix * FPITCH, embedding, fnS[pix], enS[k], k);
                    atomicMin(&bestS[pix], dist_key(r, k));
                }
            }
        }
        // flagged pixels: exact full scan (first-min by ascending k, strict <)
        if (tid < PIX && pxovf[tid]) {
            const float* fr = F32 + tid * FPITCH;
            const float  fn = fnS[tid];
            float best = FLT_MAX; int bestk = 0;
            for (int k = 0; k < KC; ++k) {
                float r = exact_dist(fr, embedding, fn, enS[k], k);
                if (r < best) { best = r; bestk = k; }
            }
            atomicMin(&bestS[tid], dist_key(best, bestk));
        }
        __syncthreads();

        // ---- phase 4: epilogue, all 256 threads (half pixel each) ----
        float ldist = 0.0f;
        {
            const int bestk = (int)(unsigned)(bestS[px] & 0xFFFFu);
            const float* fr = F32 + px * FPITCH + hh * 32;
            float* outp = out + (size_t)b * DC * HWC + hw + (size_t)(hh * 32) * HWC;
            const float4* er4 = (const float4*)(embedding + (size_t)bestk * DC + hh * 32);
            #pragma unroll
            for (int q = 0; q < 8; ++q) {
                float4 ev = __ldg(er4 + q);
                float f0 = fr[4 * q + 0], f1 = fr[4 * q + 1];
                float f2 = fr[4 * q + 2], f3 = fr[4 * q + 3];
                float d0 = __fsub_rn(ev.x, f0);
                float d1 = __fsub_rn(ev.y, f1);
                float d2 = __fsub_rn(ev.z, f2);
                float d3 = __fsub_rn(ev.w, f3);
                ldist = __fadd_rn(ldist, __fmul_rn(d0, d0));
                ldist = __fadd_rn(ldist, __fmul_rn(d1, d1));
                ldist = __fadd_rn(ldist, __fmul_rn(d2, d2));
                ldist = __fadd_rn(ldist, __fmul_rn(d3, d3));
                outp[(4 * q + 0) * HWC] = __fadd_rn(f0, d0);
                outp[(4 * q + 1) * HWC] = __fadd_rn(f1, d1);
                outp[(4 * q + 2) * HWC] = __fadd_rn(f2, d2);
                outp[(4 * q + 3) * HWC] = __fadd_rn(f3, d3);
            }
        }
        __syncthreads();            // wl dead; red overlay safe

        // ---- per-tile deterministic tree reduce -> g_part[tile] ----
        red[tid] = ldist;
        __syncthreads();
        #pragma unroll
        for (int s = TPB / 2; s > 0; s >>= 1) {
            if (tid < s) red[tid] += red[tid + s];
            __syncthreads();
        }
        if (tid == 0) g_part[tile] = red[0];
        __syncthreads();
    }

    // ---- grid finalize ----
    __shared__ unsigned s_last;
    __threadfence();
    if (tid == 0) s_last = (atomicAdd(&g_done, 1u) == GRIDP - 1u);
    __syncthreads();

    if (s_last) {
        red[tid] = (g_part[tid] + g_part[tid + 256])
                 + (g_part[tid + 512] + g_part[tid + 768]);
        __syncthreads();
        #pragma unroll
        for (int s = TPB / 2; s > 0; s >>= 1) {
            if (tid < s) red[tid] += red[tid + s];
            __syncthreads();
        }
        if (tid == 0) {
            float m = red[0] / 8388608.0f;
            *loss_out = __fadd_rn(__fmul_rn(m, 0.25f), m);
            g_done = 0;
            g_tile = 0;
        }
    }
}

extern "C" void kernel_launch(void* const* d_in, const int* in_sizes, int n_in,
                              void* d_out, int out_size) {
    const float* latents   = (const float*)d_in[0];
    const float* embedding = (const float*)d_in[1];
    float* out  = (float*)d_out;
    float* loss = out + (out_size - 1);

    cudaFuncSetAttribute(vq_kernel, cudaFuncAttributeMaxDynamicSharedMemorySize, SMEM_BYTES);
    vq_kernel<<<GRIDP, TPB, SMEM_BYTES>>>(latents, embedding, out, loss);
}

// round 16
// speedup vs baseline: 7.7887x; 4.8198x over previous
#include <cuda_runtime.h>
#include <cuda_bf16.h>
#include <float.h>
#include <stdint.h>

// Fixed problem shape
#define KC      512
#define DC      64
#define HWC     4096
#define NC      131072
#define TPB     256         // 8 warps
#define PIX     128         // pixels per tile
#define NTILES  (NC/PIX)    // 1024
#define GRIDP   256         // 2 CTAs/SM; dynamic tile stealing
#define EPITCH  72          // bf16 codebook pitch (144B rows; LDSM conflict-free)
#define FPITCH  66          // fp32 latent pitch
#define WLCAP   768

// smem layout (bytes) — identical budget to the 174.6us R13 kernel
#define OFF_ECB 0                           // bf16 [512][72]   73728
#define OFF_F32 (OFF_ECB + KC*EPITCH*2)     // fp32 [128][66]   33792
#define OFF_EN  (OFF_F32 + PIX*FPITCH*4)    // float[512]        2048
#define OFF_FN  (OFF_EN + KC*4)             // float[128]         512
#define OFF_SLK (OFF_FN + PIX*4)            // float[128]         512
#define OFF_THR (OFF_SLK + PIX*4)           // float[128]         512
#define OFF_BST (OFF_THR + PIX*4)           // u64  [128]        1024
#define OFF_WL  (OFF_BST + PIX*8)           // u32  [768]        3072 (red overlays)
#define OFF_CNT (OFF_WL + WLCAP*4)          // int + pad           16
#define SMEM_BYTES (OFF_CNT + 16)           // 115216 -> 2 CTAs/SM

__device__ float    g_part[NTILES];
__device__ unsigned g_done;
__device__ unsigned g_tile;

__device__ __forceinline__ void mma_bf16(float c[4], const unsigned a[4],
                                         unsigned b0, unsigned b1) {
    asm volatile(
        "mma.sync.aligned.m16n8k16.row.col.f32.bf16.bf16.f32 "
        "{%0,%1,%2,%3}, {%4,%5,%6,%7}, {%8,%9}, {%0,%1,%2,%3};"
        : "+f"(c[0]), "+f"(c[1]), "+f"(c[2]), "+f"(c[3])
        : "r"(a[0]), "r"(a[1]), "r"(a[2]), "r"(a[3]), "r"(b0), "r"(b1));
}

__device__ __forceinline__ void ldsm_x4(unsigned& d0, unsigned& d1,
                                        unsigned& d2, unsigned& d3,
                                        unsigned addr) {
    asm volatile(
        "ldmatrix.sync.aligned.m8n8.x4.shared.b16 {%0,%1,%2,%3}, [%4];"
        : "=r"(d0), "=r"(d1), "=r"(d2), "=r"(d3) : "r"(addr));
}

__device__ __forceinline__ unsigned pack_bf2(float2 p) {
    __nv_bfloat162 h = __float22bfloat162_rn(p);
    return *reinterpret_cast<unsigned*>(&h);
}

// exact reference-arithmetic distance for (pixel fr, code k)
__device__ __forceinline__ float exact_dist(const float* fr, const float* emb,
                                            float fn, float en, int k) {
    const float4* er4 = (const float4*)(emb + (size_t)k * DC);
    float dot = 0.0f;
    #pragma unroll
    for (int q = 0; q < 16; ++q) {
        float4 ev = __ldg(er4 + q);
        dot = fmaf(fr[4 * q + 0], ev.x, dot);
        dot = fmaf(fr[4 * q + 1], ev.y, dot);
        dot = fmaf(fr[4 * q + 2], ev.z, dot);
        dot = fmaf(fr[4 * q + 3], ev.w, dot);
    }
    return __fsub_rn(__fadd_rn(fn, en), __fmul_rn(2.0f, dot));
}

__device__ __forceinline__ unsigned long long dist_key(float r, int k) {
    unsigned rb = __float_as_uint(r);
    rb ^= (rb >> 31) ? 0xFFFFFFFFu : 0x80000000u;   // order-preserving map
    return ((unsigned long long)rb << 32) | (unsigned)k;
}

__global__ __launch_bounds__(TPB, 2)
void vq_kernel(const float* __restrict__ latents,
               const float* __restrict__ embedding,
               float* __restrict__ out,
               float* __restrict__ loss_out) {
    extern __shared__ char smem[];
    __nv_bfloat16* Ecb = (__nv_bfloat16*)(smem + OFF_ECB);
    float* F32  = (float*)(smem + OFF_F32);
    float* enS  = (float*)(smem + OFF_EN);
    float* fnS  = (float*)(smem + OFF_FN);
    float* slkS = (float*)(smem + OFF_SLK);
    float* thrS = (float*)(smem + OFF_THR);
    unsigned long long* bestS = (unsigned long long*)(smem + OFF_BST);
    unsigned* wl   = (unsigned*)(smem + OFF_WL);
    int*      wcnt = (int*)(smem + OFF_CNT);
    float*    red  = (float*)(smem + OFF_WL);   // overlay after wl dead

    const int tid  = threadIdx.x;
    const int wid  = tid >> 5;
    const int lane = tid & 31;
    const int g    = lane >> 2;
    const int tig  = lane & 3;
    const int px   = tid & (PIX - 1);   // pixel for split phases
    const int hh   = tid >> 7;          // half (0:d<32, 1:d>=32)

    // shared-state base address of Ecb for ldmatrix
    unsigned ecbA;
    asm("{ .reg .u64 t; cvta.to.shared.u64 t, %1; cvt.u32.u64 %0, t; }"
        : "=r"(ecbA) : "l"(Ecb));
    const unsigned rowoff = (unsigned)((lane & 7) * (EPITCH * 2) + (lane >> 3) * 16);

    // ---- once per CTA: bf16 codebook + exact reference enorm ----
    for (int i = tid; i < KC * DC; i += TPB) {
        int k = i >> 6, d = i & 63;
        Ecb[k * EPITCH + d] = __float2bfloat16_rn(embedding[i]);
    }
    #pragma unroll
    for (int kk = 0; kk < 2; ++kk) {
        int k = tid + kk * TPB;
        const float* er = embedding + (size_t)k * DC;
        float s = 0.0f;
        #pragma unroll
        for (int d = 0; d < DC; ++d)
            s = __fadd_rn(s, __fmul_rn(er[d], er[d]));
        enS[k] = s;
    }
    __syncthreads();

    __shared__ int  s_tile;
    __shared__ bool s_govf;

    while (true) {
        if (tid == 0) s_tile = (int)atomicAdd(&g_tile, 1u);
        __syncthreads();
        const int tile = s_tile;
        if (tile >= NTILES) break;

        const int P  = tile * PIX + px;
        const int b  = P >> 12;
        const int hw = P & (HWC - 1);
        const float* lat = latents + (size_t)b * DC * HWC + hw;

        // ---- phase 0: stage latents (all 256 threads, half-pixel each) ----
        {
            float* fr = F32 + px * FPITCH;
            #pragma unroll
            for (int j = 0; j < 32; ++j) {
                int d = hh * 32 + j;
                fr[d] = lat[d * HWC];
            }
            if (tid < PIX) bestS[tid] = 0xFFFFFFFFFFFFFFFFull;
            if (tid == 0)  { *wcnt = 0; s_govf = false; }
        }
        __syncthreads();

        // ---- fnorm (exact sequential chain) + slack, from smem ----
        if (tid < PIX) {
            const float* fr = F32 + tid * FPITCH;
            float fn = 0.0f, bnd = 0.0f;
            #pragma unroll
            for (int d = 0; d < DC; ++d) {
                float f = fr[d];
                fn = __fadd_rn(fn, __fmul_rn(f, f));
                float fb = __bfloat162float(__float2bfloat16_rn(f));
                bnd += fabsf(f) * 4.0e-6f + 1.96e-3f * fabsf(f - fb);
            }
            fnS[tid]  = fn;
            slkS[tid] = fmaf(5.0f, bnd, 1.6e-4f);
        }
        __syncthreads();

        // ---- A fragments (cvt fp32->bf16 from smem) ----
        const int r0 = wid * 16 + g;
        const int r1 = r0 + 8;
        unsigned afr[4][4];
        #pragma unroll
        for (int ks = 0; ks < 4; ++ks) {
            afr[ks][0] = pack_bf2(*(const float2*)(F32 + r0 * FPITCH + 16 * ks + 2 * tig));
            afr[ks][1] = pack_bf2(*(const float2*)(F32 + r1 * FPITCH + 16 * ks + 2 * tig));
            afr[ks][2] = pack_bf2(*(const float2*)(F32 + r0 * FPITCH + 16 * ks + 8 + 2 * tig));
            afr[ks][3] = pack_bf2(*(const float2*)(F32 + r1 * FPITCH + 16 * ks + 8 + 2 * tig));
        }

        // ---- phase 1: GEMM pass (ldmatrix B), per-pixel screening min ----
        float rm0 = FLT_MAX, rm1 = FLT_MAX;
        #pragma unroll 4
        for (int nb = 0; nb < KC / 8; ++nb) {
            const int cb = nb * 8;
            const unsigned baddr = ecbA + (unsigned)cb * (EPITCH * 2) + rowoff;
            unsigned b0, b1, b2, b3, b4, b5, b6, b7;
            ldsm_x4(b0, b1, b2, b3, baddr);          // ks0: b0,b1  ks1: b2,b3
            ldsm_x4(b4, b5, b6, b7, baddr + 64);     // ks2: b4,b5  ks3: b6,b7
            float c[4] = {0.f, 0.f, 0.f, 0.f};
            mma_bf16(c, afr[0], b0, b1);
            mma_bf16(c, afr[1], b2, b3);
            mma_bf16(c, afr[2], b4, b5);
            mma_bf16(c, afr[3], b6, b7);
            float en0 = enS[cb + 2 * tig];
            float en1 = enS[cb + 2 * tig + 1];
            rm0 = fminf(rm0, fminf(fmaf(-2.0f, c[0], en0), fmaf(-2.0f, c[1], en1)));
            rm1 = fminf(rm1, fminf(fmaf(-2.0f, c[2], en0), fmaf(-2.0f, c[3], en1)));
        }
        rm0 = fminf(rm0, __shfl_xor_sync(0xffffffffu, rm0, 1));
        rm0 = fminf(rm0, __shfl_xor_sync(0xffffffffu, rm0, 2));
        rm1 = fminf(rm1, __shfl_xor_sync(0xffffffffu, rm1, 1));
        rm1 = fminf(rm1, __shfl_xor_sync(0xffffffffu, rm1, 2));
        if (tig == 0) {
            thrS[r0] = rm0;
            thrS[r1] = rm1;
        }
        __syncthreads();
        if (tid < PIX) thrS[tid] = thrS[tid] + slkS[tid];
        __syncthreads();

        // ---- phase 2: GEMM pass (ldmatrix B), collect candidates ----
        {
            const float t0 = thrS[r0];
            const float t1 = thrS[r1];
            #pragma unroll 4
            for (int nb = 0; nb < KC / 8; ++nb) {
                const int cb = nb * 8;
                const unsigned baddr = ecbA + (unsigned)cb * (EPITCH * 2) + rowoff;
                unsigned b0, b1, b2, b3, b4, b5, b6, b7;
                ldsm_x4(b0, b1, b2, b3, baddr);
                ldsm_x4(b4, b5, b6, b7, baddr + 64);
                float c[4] = {0.f, 0.f, 0.f, 0.f};
                mma_bf16(c, afr[0], b0, b1);
                mma_bf16(c, afr[1], b2, b3);
                mma_bf16(c, afr[2], b4, b5);
                mma_bf16(c, afr[3], b6, b7);
                const int k0 = cb + 2 * tig;
                float en0 = enS[k0];
                float en1 = enS[k0 + 1];
                float s0 = fmaf(-2.0f, c[0], en0);
                float s1 = fmaf(-2.0f, c[1], en1);
                float s2 = fmaf(-2.0f, c[2], en0);
                float s3 = fmaf(-2.0f, c[3], en1);
                if (s0 <= t0) { int p_ = atomicAdd(wcnt, 1); if (p_ < WLCAP) wl[p_] = ((unsigned)r0 << 16) | (unsigned)k0; }
                if (s1 <= t0) { int p_ = atomicAdd(wcnt, 1); if (p_ < WLCAP) wl[p_] = ((unsigned)r0 << 16) | (unsigned)(k0 + 1); }
                if (s2 <= t1) { int p_ = atomicAdd(wcnt, 1); if (p_ < WLCAP) wl[p_] = ((unsigned)r1 << 16) | (unsigned)k0; }
                if (s3 <= t1) { int p_ = atomicAdd(wcnt, 1); if (p_ < WLCAP) wl[p_] = ((unsigned)r1 << 16) | (unsigned)(k0 + 1); }
            }
        }
        __syncthreads();

        // ---- phase 3: parallel exact recheck over all pairs ----
        if (tid == 0 && *wcnt > WLCAP) s_govf = true;
        __syncthreads();
        const bool govf = s_govf;
        if (!govf) {
            const int nw = *wcnt;
            for (int i = tid; i < nw; i += TPB) {
                unsigned e = wl[i];
                int pix = (int)(e >> 16);
                int k   = (int)(e & 0xFFFFu);
                float r = exact_dist(F32 + pix * FPITCH, embedding, fnS[pix], enS[k], k);
                atomicMin(&bestS[pix], dist_key(r, k));
            }
        } else if (tid < PIX) {
            // overflow fallback: full exact scan (correct by construction)
            const float* fr = F32 + tid * FPITCH;
            const float  fn = fnS[tid];
            float best = FLT_MAX; int bestk = 0;
            for (int k = 0; k < KC; ++k) {
                float r = exact_dist(fr, embedding, fn, enS[k], k);
                if (r < best) { best = r; bestk = k; }   // ascending k => first-min
            }
            atomicMin(&bestS[tid], dist_key(best, bestk));
        }
        __syncthreads();

        // ---- phase 4: epilogue, all 256 threads (half pixel each) ----
        float ldist = 0.0f;
        {
            const int bestk = (int)(unsigned)(bestS[px] & 0xFFFFu);
            const float* fr = F32 + px * FPITCH + hh * 32;
            float* outp = out + (size_t)b * DC * HWC + hw + (size_t)(hh * 32) * HWC;
            const float4* er4 = (const float4*)(embedding + (size_t)bestk * DC + hh * 32);
            #pragma unroll
            for (int q = 0; q < 8; ++q) {
                float4 ev = __ldg(er4 + q);
                float f0 = fr[4 * q + 0], f1 = fr[4 * q + 1];
                float f2 = fr[4 * q + 2], f3 = fr[4 * q + 3];
                float d0 = __fsub_rn(ev.x, f0);
                float d1 = __fsub_rn(ev.y, f1);
                float d2 = __fsub_rn(ev.z, f2);
                float d3 = __fsub_rn(ev.w, f3);
                ldist = __fadd_rn(ldist, __fmul_rn(d0, d0));
                ldist = __fadd_rn(ldist, __fmul_rn(d1, d1));
                ldist = __fadd_rn(ldist, __fmul_rn(d2, d2));
                ldist = __fadd_rn(ldist, __fmul_rn(d3, d3));
                outp[(4 * q + 0) * HWC] = __fadd_rn(f0, d0);
                outp[(4 * q + 1) * HWC] = __fadd_rn(f1, d1);
                outp[(4 * q + 2) * HWC] = __fadd_rn(f2, d2);
                outp[(4 * q + 3) * HWC] = __fadd_rn(f3, d3);
            }
        }
        __syncthreads();            // wl dead; red overlay safe

        // ---- per-tile deterministic tree reduce -> g_part[tile] ----
        red[tid] = ldist;
        __syncthreads();
        #pragma unroll
        for (int s = TPB / 2; s > 0; s >>= 1) {
            if (tid < s) red[tid] += red[tid + s];
            __syncthreads();
        }
        if (tid == 0) g_part[tile] = red[0];
        __syncthreads();
    }

    // ---- grid finalize ----
    __shared__ unsigned s_last;
    __threadfence();
    if (tid == 0) s_last = (atomicAdd(&g_done, 1u) == GRIDP - 1u);
    __syncthreads();

    if (s_last) {
        red[tid] = (g_part[tid] + g_part[tid + 256])
                 + (g_part[tid + 512] + g_part[tid + 768]);
        __syncthreads();
        #pragma unroll
        for (int s = TPB / 2; s > 0; s >>= 1) {
            if (tid < s) red[tid] += red[tid + s];
            __syncthreads();
        }
        if (tid == 0) {
            float m = red[0] / 8388608.0f;
            *loss_out = __fadd_rn(__fmul_rn(m, 0.25f), m);
            g_done = 0;
            g_tile = 0;
        }
    }
}

extern "C" void kernel_launch(void* const* d_in, const int* in_sizes, int n_in,
                              void* d_out, int out_size) {
    const float* latents   = (const float*)d_in[0];
    const float* embedding = (const float*)d_in[1];
    float* out  = (float*)d_out;
    float* loss = out + (out_size - 1);

    cudaFuncSetAttribute(vq_kernel, cudaFuncAttributeMaxDynamicSharedMemorySize, SMEM_BYTES);
    vq_kernel<<<GRIDP, TPB, SMEM_BYTES>>>(latents, embedding, out, loss);
}